// round 11
// baseline (speedup 1.0000x reference)
#include <cuda_runtime.h>
#include <cuda_fp16.h>
#include <cstdint>
#include <math.h>
#include <float.h>

#define D_TOT   496
#define F_TOT   40
#define T_STEPS 1000
#define GROUPS  8
#define GCOLS   62
#define NT      296
#define RMAX    128
#define FULLM   0xFFFFFFFFu

// ---------------- device scratch ----------------
__device__ float4 g_tabA[T_STEPS * 5];   // (qb1, qb1e, qow, qowe)
__device__ float4 g_tabB[T_STEPS * 5];   // (evh, evhe, evc, evce)
__device__ float2 g_tabC[T_STEPS * 5];   // (cam, qbme)
__device__ float4 g_tabD[T_STEPS * 5];   // (n1_same, inv1_same, n1_diff, inv1_diff)
__device__ float4 g_smp [T_STEPS * 5];   // (qb, qhot, kpow, 0)
__device__ float  g_prior;
__device__ float  g_part[512 * 16];

// ---------------- helpers ----------------
__device__ __forceinline__ float lae_prec(float a, float b) {
    float m = fmaxf(a, b), n = fminf(a, b);
    return m + log1pf(expf(n - m));
}

// Lane layout: each lane owns 2 adjacent columns of ONE feature.
// Feature sizes 2,4,8,16,32 at group-local cols [0,2),[2,6),[6,14),[14,30),[30,62).
struct Lane { int la, widthL, lbase, cp, sstart; float lnc; unsigned segm; };
__device__ __forceinline__ Lane laneLayout(int lane) {
    Lane L;
    if (lane < 16)      { L.la=4; L.widthL=16; L.lbase=0;  L.cp=15+lane; L.sstart=30; L.lnc=3.46573590f; L.segm=0x0000FFFFu; }
    else if (lane < 24) { L.la=3; L.widthL=8;  L.lbase=16; L.cp=lane-9;  L.sstart=14; L.lnc=2.77258872f; L.segm=0x00FF0000u; }
    else if (lane < 28) { L.la=2; L.widthL=4;  L.lbase=24; L.cp=lane-21; L.sstart=6;  L.lnc=2.07944154f; L.segm=0x0F000000u; }
    else if (lane < 30) { L.la=1; L.widthL=2;  L.lbase=28; L.cp=lane-27; L.sstart=2;  L.lnc=1.38629436f; L.segm=0x30000000u; }
    else if (lane == 30){ L.la=0; L.widthL=1;  L.lbase=30; L.cp=0;       L.sstart=0;  L.lnc=0.69314718f; L.segm=0x40000000u; }
    else                { L.la=0; L.widthL=0;  L.lbase=31; L.cp=0;       L.sstart=0;  L.lnc=0.69314718f; L.segm=0x80000000u; }
    return L;
}
__device__ __forceinline__ int cpOfLane(int l) {
    return (l < 16) ? 15 + l : (l < 24) ? l - 9 : (l < 28) ? l - 21 : (l < 30) ? l - 27 : 0;
}
__device__ __forceinline__ int cpToLane(int cp) {
    return (cp >= 15) ? cp - 15 : (cp >= 7) ? cp + 9 : (cp >= 3) ? cp + 21
         : (cp >= 1) ? cp + 27 : 30;
}
__device__ __forceinline__ float segMax(float v, int widthL) {
#pragma unroll
    for (int d = 1; d < 16; d <<= 1) {
        float o = __shfl_xor_sync(FULLM, v, d);
        if (widthL > d) v = fmaxf(v, o);
    }
    return v;
}
__device__ __forceinline__ float segSum(float v, int widthL) {
#pragma unroll
    for (int d = 1; d < 16; d <<= 1) {
        float o = __shfl_xor_sync(FULLM, v, d);
        if (widthL > d) v += o;
    }
    return v;
}

// ---------------- prologue: scan + all tables ----------------
__global__ void __launch_bounds__(1024) k_prep() {
    __shared__ float shi[1024], slo[1024], sla[1024], sl1b[1024], sl1c[1024];
    const int tid = threadIdx.x;
    float la = 0.f, l1b = 0.f;
    if (tid < T_STEPS) {
        double beta = 1e-4 + (double)tid * ((0.02 - 1e-4) / 999.0);
        float betaf = (float)beta;
        la  = log1pf(-betaf);
        l1b = logf(betaf);
    }
    sla[tid] = la; sl1b[tid] = l1b;
    shi[tid] = la; slo[tid] = 0.f;
    __syncthreads();
    for (int off = 1; off < 1024; off <<= 1) {
        float ahi = (tid >= off) ? shi[tid - off] : 0.f;
        float alo = (tid >= off) ? slo[tid - off] : 0.f;
        __syncthreads();
        float x = shi[tid];
        float s = x + ahi;
        float bb = s - x;
        float err = (x - (s - bb)) + (ahi - bb);
        float lo = err + slo[tid] + alo;
        float hi2 = s + lo;
        lo = lo - (hi2 - s);
        shi[tid] = hi2; slo[tid] = lo;
        __syncthreads();
    }
    if (tid < T_STEPS) sl1c[tid] = logf(-expm1f(shi[tid]));
    __syncthreads();

    const float lncs[5] = {0.69314718f, 1.38629436f, 2.07944154f, 2.77258872f, 3.46573590f};
    const int   Ks[5]   = {2, 4, 8, 16, 32};
    const float LOGEPS = -69.07755279f;
    for (int i = tid; i < T_STEPS * 5; i += 1024) {
        const int t = i / 5, laid = i - 5 * t;
        const float lnc = lncs[laid];
        const int K = Ks[laid];

        const float qb1 = sl1b[t] - lnc;
        const float qow = lae_prec(sla[t], qb1);
        const float qb1e = expf(qb1), qowe = expf(qow);

        float cam, qbme, evh, evhe, evc, evce;
        if (t == 0) {
            cam = 1.f; qbme = 0.f;
            evh = 0.f; evhe = 1.f;
            evc = LOGEPS; evce = 1e-30f;
        } else {
            const float lcm = shi[t - 1];
            const float qbm = sl1c[t - 1] - lnc;
            cam = expf(lcm);
            qbme = expf(qbm);
            evh = lae_prec(lcm, qbm);
            evhe = expf(evh);
            evc = qbm; evce = qbme;
        }
        g_tabA[i] = make_float4(qb1, qb1e, qow, qowe);
        g_tabB[i] = make_float4(evh, evhe, evc, evce);
        g_tabC[i] = make_float2(cam, qbme);

        const float s1s = evhe * qowe + (float)(K - 1) * evce * qb1e;
        const float s1d = evhe * qb1e + evce * qowe + (float)(K - 2) * evce * qb1e;
        g_tabD[i] = make_float4(logf(s1s), 1.f / s1s, logf(s1d), 1.f / s1d);

        const float qb = sl1c[t] - lnc;
        const float qhot = lae_prec(shi[t], qb);
        g_smp[i] = make_float4(qb, qhot, expf(qhot - qb), 0.f);
    }
    __syncthreads();
    if (tid == 0) {
        float P = 0.f;
        for (int laid = 0; laid < 5; laid++) {
            const float lnc = lncs[laid];
            const float qbT = sl1c[T_STEPS - 1] - lnc;
            const float lqh = lae_prec(shi[T_STEPS - 1], qbT);
            const float prh = expf(lqh) * (lqh + lnc);
            const float prc = expf(qbT) * (qbT + lnc);
            P += prh + (float)(Ks[laid] - 1) * prc;
        }
        g_prior = 8.f * P;
    }
}

// ---------------- mega kernel: sample + gather + posteriors + KL ----------------
// smem (bytes):
//   [0, 61504)          sW    half2[496*31]
//   [61504, 81984)      sOff  int[RMAX*40]   premult winner offsets (win_global*124)
//   [81984, 102464)     sPack int[RMAX*40]   (hot_global<<16)|win_global
//   [102464, 102976)    sTs   int[RMAX]
//   [102976, 103224)    sCs   float2[31]
//   [103224, 107192)    sScr  float2[16*31]  colsum partials
#define SM_OFF  61504
#define SM_PACK (SM_OFF  + RMAX * F_TOT * 4)
#define SM_TS   (SM_PACK + RMAX * F_TOT * 4)
#define SM_CS   (SM_TS   + RMAX * 4)
#define SM_SCR  (SM_CS   + 31 * 8)
#define SM_TOT  (SM_SCR  + 16 * 31 * 8)

__global__ void __launch_bounds__(512, 2) k_fuse(
    const int* __restrict__ x0, const int* __restrict__ ts,
    const float* __restrict__ uni, const float* __restrict__ W,
    const float* __restrict__ bias, const float* __restrict__ temb, int B)
{
    extern __shared__ char smem[];
    half2*  sW    = (half2*)smem;
    int*    sOff  = (int*)(smem + SM_OFF);
    int*    sPack = (int*)(smem + SM_PACK);
    int*    sTs   = (int*)(smem + SM_TS);
    float2* sCs   = (float2*)(smem + SM_CS);
    float2* sScr  = (float2*)(smem + SM_SCR);

    const int tid = threadIdx.x, lane = tid & 31, wid = tid >> 5;
    const int per = (B + gridDim.x - 1) / gridDim.x;
    const int r0 = blockIdx.x * per;
    const int nrows = min(per, B - r0);

    Lane L = laneLayout(lane);
    const bool valid = (L.widthL > 0);
    const int c0 = 2 * L.cp;                 // group-local col of slot 0
    const float NEG = -FLT_MAX;
    const float LOGEPS = -69.07755279f;
    const char* sWb = smem;
    const int cpb = L.cp * 4;

    // ---- stage ts ----
    for (int i = tid; i < nrows; i += 512) sTs[i] = __ldg(&ts[r0 + i]);
    __syncthreads();

    // ---- phase 1: inline Gumbel-max sampling for all (row, group) ----
    for (int task = wid; task < nrows * GROUPS; task += 16) {
        const int row = task >> 3, g = task & 7;
        const int t = sTs[row];
        const float4 sm = __ldg(&g_smp[t * 5 + L.la]);
        const int feat = g * 5 + L.la;
        const int x0v = valid ? __ldg(&x0[(r0 + row) * F_TOT + feat]) : 0;
        const int hot = L.sstart + x0v;      // group-local

        float2 u = make_float2(0.f, 0.f);
        if (valid) u = *(const float2*)(uni + (size_t)(r0 + row) * D_TOT + g * GCOLS + c0);

        // non-hot u-max (gumbel monotone in u), ballot index recovery
        const float un0 = (!valid || c0 == hot)     ? -1.f : u.x;
        const float un1 = (!valid || c0 + 1 == hot) ? -1.f : u.y;
        float uv = fmaxf(un0, un1);
        uv = segMax(uv, L.widthL);
        const unsigned b0 = __ballot_sync(FULLM, un0 == uv);
        const unsigned b1 = __ballot_sync(FULLM, un1 == uv);
        const unsigned cand = (b0 | b1) & L.segm;
        const int wl = __ffs(cand) - 1;                 // lowest lane = min col
        const int wcp = cpOfLane(wl);
        const int ui = 2 * wcp + (((b0 >> wl) & 1u) ? 0 : 1);

        const int hlane = cpToLane(hot >> 1);
        const float uh = __shfl_sync(FULLM, (hot & 1) ? u.y : u.x, hlane);

        int win = ui;
        if (valid) {
            // hot wins iff ln(uh+eps) > k * ln(uv+eps)
            const float lnv = __logf(uv + 1e-30f);
            const float lnh = __logf(uh + 1e-30f);
            const float d2 = lnh - sm.z * lnv;
            const float mar = 1e-3f * (-lnh);
            if (uv > 0.996f || uh > 0.996f || fabsf(d2) < mar) {
                const float gb = -logf(-logf(uv + 1e-30f) + 1e-30f);
                const float gh = -logf(-logf(uh + 1e-30f) + 1e-30f);
                const float zb = sm.x + gb;
                const float zh = sm.y + gh;
                win = (zh > zb) ? hot : ((zh == zb) ? min(hot, ui) : ui);
            } else {
                win = (d2 > 0.f) ? hot : ui;
            }
        }
        if (valid && lane == L.lbase) {
            const int wing = g * GCOLS + win;
            const int hotg = g * GCOLS + hot;
            sOff[row * F_TOT + feat] = wing * 124;
            sPack[row * F_TOT + feat] = (hotg << 16) | wing;
        }
    }

    // ---- phase 2: per-group staging + posterior math ----
    float lacc = 0.f;
    for (int g = 0; g < GROUPS; g++) {
        const int gbase = g * GCOLS;
        __syncthreads();                     // protect sW reuse
        // stage W group -> fp16, fp32 colsum partials
        float2 acc = make_float2(0.f, 0.f);
        for (int r = wid; r < D_TOT; r += 16) {
            if (lane < 31) {
                float2 v = *(const float2*)(W + (size_t)r * D_TOT + gbase + 2 * lane);
                acc.x += v.x; acc.y += v.y;
                sW[r * 31 + lane] = __floats2half2_rn(v.x, v.y);
            }
        }
        if (lane < 31) sScr[wid * 31 + lane] = acc;
        __syncthreads();
        if (tid < 31) {
            float2 s = make_float2(0.f, 0.f);
#pragma unroll
            for (int w2 = 0; w2 < 16; w2++) { float2 a = sScr[w2 * 31 + tid]; s.x += a.x; s.y += a.y; }
            sCs[tid] = s;
        }
        __syncthreads();

        const float2 cs2 = sCs[L.cp];
        const int C0 = gbase + 2 * L.cp;
        const int feat = g * 5 + L.la;
        const float2 b2 = *(const float2*)(bias + C0);

        for (int rl = wid; rl < nrows; rl += 16) {
            const int t = sTs[rl];
            const int ti = t * 5 + L.la;
            const float4 A  = __ldg(&g_tabA[ti]);
            const float4 Bv = __ldg(&g_tabB[ti]);
            const float2 Cv = __ldg(&g_tabC[ti]);
            const float4 Dv = __ldg(&g_tabD[ti]);
            const bool t0 = (t == 0);
            const int pack = sPack[rl * F_TOT + feat];
            const int hotc = pack >> 16, winc = pack & 0xFFFF;
            const bool h0 = (hotc == C0), h1 = (hotc == C0 + 1);
            const bool w0 = (winc == C0), w1 = (winc == C0 + 1);
            const bool same = (hotc == winc);
            const float n1 = same ? Dv.x : Dv.z;
            const float inv1k = (same ? Dv.y : Dv.w) * 1000.f;

            // gather: 40 fp16 winner rows
            const int4* op = (const int4*)(sOff + rl * F_TOT);
            half2 a0 = __float2half2_rn(0.f), a1 = a0, a2 = a0, a3 = a0;
#pragma unroll
            for (int q = 0; q < 10; q++) {
                int4 o = op[q];
                a0 = __hadd2(a0, *(const half2*)(sWb + o.x + cpb));
                a1 = __hadd2(a1, *(const half2*)(sWb + o.y + cpb));
                a2 = __hadd2(a2, *(const half2*)(sWb + o.z + cpb));
                a3 = __hadd2(a3, *(const half2*)(sWb + o.w + cpb));
            }
            const float2 w2 = __half22float2(__hadd2(__hadd2(a0, a1), __hadd2(a2, a3)));

            const float2 te = *(const float2*)(temb + (size_t)t * D_TOT + C0);
            const float p0 = LOGEPS * (cs2.x - w2.x) + b2.x + te.x;
            const float p1 = LOGEPS * (cs2.y - w2.y) + b2.y + te.y;

            // per-segment softmax (exp-domain)
            float m = valid ? fmaxf(p0, p1) : NEG;
            m = segMax(m, L.widthL);
            const float E0 = valid ? __expf(p0 - m) : 0.f;
            const float E1 = valid ? __expf(p1 - m) : 0.f;
            const float s = segSum(E0 + E1, L.widthL);
            const float invs = __fdividef(1.f, s);
            const float lses = __logf(s);

            const float xe20 = E0 * invs * Cv.x + Cv.y;
            const float xe21 = E1 * invs * Cv.x + Cv.y;
            const float e2l0 = t0 ? (p0 - m - lses) : __logf(xe20);
            const float e2l1 = t0 ? (p1 - m - lses) : __logf(xe21);

            const float qo0e = w0 ? A.w : A.y, qo1e = w1 ? A.w : A.y;
            const float ev0l = h0 ? Bv.x : Bv.z, ev1l = h1 ? Bv.x : Bv.z;
            const float ev0e = h0 ? Bv.y : Bv.w, ev1e = h1 ? Bv.y : Bv.w;

            const float ew0 = xe20 * qo0e, ew1 = xe21 * qo1e;
            const float s2 = segSum((valid ? ew0 : 0.f) + (valid ? ew1 : 0.f), L.widthL);
            const float n2 = __logf(s2);
            const float dn = n2 - n1;

            if (!t0) {
                const float eu0 = ev0e * qo0e, eu1 = ev1e * qo1e;
                const float klsum = eu0 * (ev0l - e2l0 + dn) + eu1 * (ev1l - e2l1 + dn);
                lacc += valid ? (klsum * inv1k) : 0.f;
            } else {
                const float qo0l = w0 ? A.z : A.x, qo1l = w1 ? A.z : A.x;
                const float deL = (h0 ? (n2 - e2l0 - qo0l) : 0.f) + (h1 ? (n2 - e2l1 - qo1l) : 0.f);
                lacc += valid ? (deL * 1000.f) : 0.f;
            }
        }
    }

#pragma unroll
    for (int d = 1; d < 32; d <<= 1)
        lacc += __shfl_xor_sync(FULLM, lacc, d);
    if (lane == 0)
        g_part[blockIdx.x * 16 + wid] = lacc;
}

// ---------------- deterministic single-kernel mean ----------------
__global__ void k_red(float* __restrict__ out, int B, int n) {
    __shared__ float s[1024];
    const int tid = threadIdx.x;
    float a = 0.f;
    for (int i = tid; i < n; i += 1024) a += g_part[i];
    s[tid] = a;
    __syncthreads();
    for (int off = 512; off > 0; off >>= 1) {
        if (tid < off) s[tid] += s[tid + off];
        __syncthreads();
    }
    if (tid == 0) out[0] = s[0] / (float)B + g_prior;
}

// ---------------- launch ----------------
extern "C" void kernel_launch(void* const* d_in, const int* in_sizes, int n_in,
                              void* d_out, int out_size) {
    const int*   x0   = (const int*)d_in[0];
    const int*   ts   = (const int*)d_in[1];
    const float* uni  = (const float*)d_in[2];
    const float* W    = (const float*)d_in[3];
    const float* bias = (const float*)d_in[4];
    const float* temb = (const float*)d_in[5];
    float* out = (float*)d_out;
    const int B = in_sizes[1];

    int nt = NT;
    if ((B + nt - 1) / nt > RMAX) nt = (B + RMAX - 1) / RMAX;
    if (nt > 512) nt = 512;

    cudaFuncSetAttribute(k_fuse, cudaFuncAttributeMaxDynamicSharedMemorySize, SM_TOT);

    k_prep<<<1, 1024>>>();
    k_fuse<<<nt, 512, SM_TOT>>>(x0, ts, uni, W, bias, temb, B);
    k_red<<<1, 1024>>>(out, B, nt * 16);
}

// round 12
// speedup vs baseline: 1.0944x; 1.0944x over previous
#include <cuda_runtime.h>
#include <cuda_fp16.h>
#include <cstdint>
#include <math.h>
#include <float.h>

#define D_TOT   496
#define F_TOT   40
#define T_STEPS 1000
#define B_MAX   32768
#define GROUPS  8
#define GCOLS   62
#define NTILES  36
#define CHUNK   128
#define FULLM   0xFFFFFFFFu

// ---------------- device scratch ----------------
__device__ float4 g_tabA[T_STEPS * 5];   // (qb1, qb1e, qow, qowe)
__device__ float4 g_tabB[T_STEPS * 5];   // (evh, evhe, evc, evce)
__device__ float2 g_tabC[T_STEPS * 5];   // (cam, qbme)
__device__ float4 g_tabD[T_STEPS * 5];   // (n1_same, inv1_same, n1_diff, inv1_diff)
__device__ float4 g_smp [T_STEPS * 5];   // (qb, qhot, kpow, 0)
__device__ float  g_prior;
__device__ int    g_win[B_MAX * F_TOT];  // packed: (hot_global<<16)|win_global
__device__ float  g_part[NTILES * GROUPS * 16];

// ---------------- helpers ----------------
__device__ __forceinline__ float lae_prec(float a, float b) {
    float m = fmaxf(a, b), n = fminf(a, b);
    return m + log1pf(expf(n - m));
}

// Lane layout: each lane owns 2 adjacent columns of ONE feature.
// Feature sizes 2,4,8,16,32 at group-local cols [0,2),[2,6),[6,14),[14,30),[30,62).
struct Lane { int la, widthL, lbase, cp, sstart; float lnc; unsigned segm; };
__device__ __forceinline__ Lane laneLayout(int lane) {
    Lane L;
    if (lane < 16)      { L.la=4; L.widthL=16; L.lbase=0;  L.cp=15+lane; L.sstart=30; L.lnc=3.46573590f; L.segm=0x0000FFFFu; }
    else if (lane < 24) { L.la=3; L.widthL=8;  L.lbase=16; L.cp=lane-9;  L.sstart=14; L.lnc=2.77258872f; L.segm=0x00FF0000u; }
    else if (lane < 28) { L.la=2; L.widthL=4;  L.lbase=24; L.cp=lane-21; L.sstart=6;  L.lnc=2.07944154f; L.segm=0x0F000000u; }
    else if (lane < 30) { L.la=1; L.widthL=2;  L.lbase=28; L.cp=lane-27; L.sstart=2;  L.lnc=1.38629436f; L.segm=0x30000000u; }
    else if (lane == 30){ L.la=0; L.widthL=1;  L.lbase=30; L.cp=0;       L.sstart=0;  L.lnc=0.69314718f; L.segm=0x40000000u; }
    else                { L.la=0; L.widthL=0;  L.lbase=31; L.cp=0;       L.sstart=0;  L.lnc=0.69314718f; L.segm=0x80000000u; }
    return L;
}
__device__ __forceinline__ int cpOfLane(int l) {
    return (l < 16) ? 15 + l : (l < 24) ? l - 9 : (l < 28) ? l - 21 : (l < 30) ? l - 27 : 0;
}
__device__ __forceinline__ int cpToLane(int cp) {
    return (cp >= 15) ? cp - 15 : (cp >= 7) ? cp + 9 : (cp >= 3) ? cp + 21
         : (cp >= 1) ? cp + 27 : 30;
}
__device__ __forceinline__ float segMax(float v, int widthL) {
#pragma unroll
    for (int d = 1; d < 16; d <<= 1) {
        float o = __shfl_xor_sync(FULLM, v, d);
        if (widthL > d) v = fmaxf(v, o);
    }
    return v;
}
__device__ __forceinline__ float segSum(float v, int widthL) {
#pragma unroll
    for (int d = 1; d < 16; d <<= 1) {
        float o = __shfl_xor_sync(FULLM, v, d);
        if (widthL > d) v += o;
    }
    return v;
}

// ---------------- prologue: scan (redundant per CTA) + partitioned tables ----------------
__global__ void __launch_bounds__(1024) k_prep() {
    __shared__ float shi[1024], slo[1024], sla[1024], sl1b[1024], sl1c[1024];
    const int tid = threadIdx.x;
    float la = 0.f, l1b = 0.f;
    if (tid < T_STEPS) {
        double beta = 1e-4 + (double)tid * ((0.02 - 1e-4) / 999.0);
        float betaf = (float)beta;
        la  = log1pf(-betaf);
        l1b = logf(betaf);
    }
    sla[tid] = la; sl1b[tid] = l1b;
    shi[tid] = la; slo[tid] = 0.f;
    __syncthreads();
    for (int off = 1; off < 1024; off <<= 1) {
        float ahi = (tid >= off) ? shi[tid - off] : 0.f;
        float alo = (tid >= off) ? slo[tid - off] : 0.f;
        __syncthreads();
        float x = shi[tid];
        float s = x + ahi;
        float bb = s - x;
        float err = (x - (s - bb)) + (ahi - bb);
        float lo = err + slo[tid] + alo;
        float hi2 = s + lo;
        lo = lo - (hi2 - s);
        shi[tid] = hi2; slo[tid] = lo;
        __syncthreads();
    }
    if (tid < T_STEPS) sl1c[tid] = logf(-expm1f(shi[tid]));
    __syncthreads();

    const float lncs[5] = {0.69314718f, 1.38629436f, 2.07944154f, 2.77258872f, 3.46573590f};
    const int   Ks[5]   = {2, 4, 8, 16, 32};
    const float LOGEPS = -69.07755279f;
    for (int i = blockIdx.x * 1024 + tid; i < T_STEPS * 5; i += gridDim.x * 1024) {
        const int t = i / 5, laid = i - 5 * t;
        const float lnc = lncs[laid];
        const int K = Ks[laid];

        const float qb1 = sl1b[t] - lnc;
        const float qow = lae_prec(sla[t], qb1);
        const float qb1e = expf(qb1), qowe = expf(qow);

        float cam, qbme, evh, evhe, evc, evce;
        if (t == 0) {
            cam = 1.f; qbme = 0.f;
            evh = 0.f; evhe = 1.f;
            evc = LOGEPS; evce = 1e-30f;
        } else {
            const float lcm = shi[t - 1];
            const float qbm = sl1c[t - 1] - lnc;
            cam = expf(lcm);
            qbme = expf(qbm);
            evh = lae_prec(lcm, qbm);
            evhe = expf(evh);
            evc = qbm; evce = qbme;
        }
        g_tabA[i] = make_float4(qb1, qb1e, qow, qowe);
        g_tabB[i] = make_float4(evh, evhe, evc, evce);
        g_tabC[i] = make_float2(cam, qbme);

        const float s1s = evhe * qowe + (float)(K - 1) * evce * qb1e;
        const float s1d = evhe * qb1e + evce * qowe + (float)(K - 2) * evce * qb1e;
        g_tabD[i] = make_float4(logf(s1s), 1.f / s1s, logf(s1d), 1.f / s1d);

        const float qb = sl1c[t] - lnc;
        const float qhot = lae_prec(shi[t], qb);
        g_smp[i] = make_float4(qb, qhot, expf(qhot - qb), 0.f);
    }
    if (blockIdx.x == 0 && tid == 0) {
        float P = 0.f;
        for (int laid = 0; laid < 5; laid++) {
            const float lnc = lncs[laid];
            const float qbT = sl1c[T_STEPS - 1] - lnc;
            const float lqh = lae_prec(shi[T_STEPS - 1], qbT);
            const float prh = expf(lqh) * (lqh + lnc);
            const float prc = expf(qbT) * (qbT + lnc);
            P += prh + (float)(Ks[laid] - 1) * prc;
        }
        g_prior = 8.f * P;
    }
}

// ---------------- K1: persistent Gumbel-max sampler (ballot argmax) ----------------
__global__ void __launch_bounds__(1024) k_sample(
    const int* __restrict__ x0, const int* __restrict__ ts,
    const float* __restrict__ uni, int B)
{
    const int lane = threadIdx.x & 31;
    Lane L = laneLayout(lane);
    const bool valid = (L.widthL > 0);
    const int c0 = 2 * L.cp;
    const int gw0 = (blockIdx.x * 1024 + threadIdx.x) >> 5;
    const int nw = (gridDim.x * 1024) >> 5;
    const int ntask = B * GROUPS;

    for (int task = gw0; task < ntask; task += nw) {
        const int row = task >> 3, g = task & 7;
        const int t = __ldg(&ts[row]);
        const float4 sm = __ldg(&g_smp[t * 5 + L.la]);
        const int feat = g * 5 + L.la;
        const int x0v = valid ? __ldg(&x0[row * F_TOT + feat]) : 0;
        const int hot = L.sstart + x0v;

        float2 u = make_float2(0.f, 0.f);
        if (valid) u = *(const float2*)(uni + (size_t)row * D_TOT + g * GCOLS + c0);

        // non-hot u-max (gumbel monotone in u), ballot index recovery
        const float un0 = (!valid || c0 == hot)     ? -1.f : u.x;
        const float un1 = (!valid || c0 + 1 == hot) ? -1.f : u.y;
        float uv = fmaxf(un0, un1);
        uv = segMax(uv, L.widthL);
        const unsigned b0 = __ballot_sync(FULLM, un0 == uv);
        const unsigned b1 = __ballot_sync(FULLM, un1 == uv);
        const unsigned cand = (b0 | b1) & L.segm;
        const int wl = __ffs(cand) - 1;                 // lowest lane = min col
        const int ui = 2 * cpOfLane(wl) + (((b0 >> wl) & 1u) ? 0 : 1);

        const int hlane = cpToLane(hot >> 1);
        const float uh = __shfl_sync(FULLM, (hot & 1) ? u.y : u.x, hlane);

        int win = ui;
        if (valid) {
            // hot wins iff ln(uh+eps) > k * ln(uv+eps)
            const float lnv = __logf(uv + 1e-30f);
            const float lnh = __logf(uh + 1e-30f);
            const float d2 = lnh - sm.z * lnv;
            const float mar = 1e-3f * (-lnh);
            if (uv > 0.996f || uh > 0.996f || fabsf(d2) < mar) {
                const float gb = -logf(-logf(uv + 1e-30f) + 1e-30f);
                const float gh = -logf(-logf(uh + 1e-30f) + 1e-30f);
                const float zb = sm.x + gb;
                const float zh = sm.y + gh;
                win = (zh > zb) ? hot : ((zh == zb) ? min(hot, ui) : ui);
            } else {
                win = (d2 > 0.f) ? hot : ui;
            }
        }
        if (valid && lane == L.lbase)
            g_win[row * F_TOT + feat] = ((g * GCOLS + hot) << 16) | (g * GCOLS + win);
    }
}

// ---------------- K2: fused gather + posteriors + KL ----------------
// 512 threads, 2 CTAs/SM. smem (bytes):
//   [0, 61504)          sW    half2[496*31]
//   [61504, 81984)      sOff  int[CHUNK*40]   (union: colsum scratch)
//   [81984, 102464)     sPack int[CHUNK*40]
//   [102464, 102712)    sCs   float2[31]
//   [102712, 103224)    sTs   int[CHUNK]
#define SMEM_OFF  61504
#define SMEM_PACK (SMEM_OFF + CHUNK * F_TOT * 4)
#define SMEM_CS   (SMEM_PACK + CHUNK * F_TOT * 4)
#define SMEM_TS   (SMEM_CS + 31 * 8)
#define SMEM_K2   (SMEM_TS + CHUNK * 4 + 8)

__global__ void __launch_bounds__(512, 2) k_fuse(
    const int* __restrict__ ts,
    const float* __restrict__ W, const float* __restrict__ bias,
    const float* __restrict__ temb, int B)
{
    extern __shared__ char smem[];
    half2*  sW    = (half2*)smem;
    int*    sOff  = (int*)(smem + SMEM_OFF);
    float2* sScr  = (float2*)(smem + SMEM_OFF);
    int*    sPack = (int*)(smem + SMEM_PACK);
    float2* sCs   = (float2*)(smem + SMEM_CS);
    int*    sTs   = (int*)(smem + SMEM_TS);

    const int g = blockIdx.y;
    const int tid = threadIdx.x, lane = tid & 31, wid = tid >> 5;
    const int gbase = g * GCOLS;

    // ---- stage W -> fp16 smem, exact fp32 colsum ----
    float2 acc = make_float2(0.f, 0.f);
    for (int r = wid; r < D_TOT; r += 16) {
        if (lane < 31) {
            float2 v = *(const float2*)(W + (size_t)r * D_TOT + gbase + 2 * lane);
            acc.x += v.x; acc.y += v.y;
            sW[r * 31 + lane] = __floats2half2_rn(v.x, v.y);
        }
    }
    if (lane < 31) sScr[wid * 31 + lane] = acc;
    __syncthreads();
    if (tid < 31) {
        float2 s = make_float2(0.f, 0.f);
#pragma unroll
        for (int w2 = 0; w2 < 16; w2++) { float2 a = sScr[w2 * 31 + tid]; s.x += a.x; s.y += a.y; }
        sCs[tid] = s;
    }
    __syncthreads();

    Lane L = laneLayout(lane);
    const bool valid = (L.widthL > 0);
    const float2 cs2 = sCs[L.cp];

    const int per = (B + gridDim.x - 1) / gridDim.x;
    const int r0 = blockIdx.x * per;
    const int r1 = min(r0 + per, B);

    const int C0 = gbase + 2 * L.cp;
    const int feat = g * 5 + L.la;
    const float LOGEPS = -69.07755279f;
    const float2 b2 = *(const float2*)(bias + C0);
    const float NEG = -FLT_MAX;

    const char* sWb = smem;
    const int cpb = L.cp * 4;

    float lacc = 0.f;

    for (int cr = r0; cr < r1; cr += CHUNK) {
        __syncthreads();
        const int nrows = min(CHUNK, r1 - cr);
        for (int i = tid; i < nrows * F_TOT; i += 512) {
            const int p = __ldg(&g_win[cr * F_TOT + i]);
            sPack[i] = p;
            sOff[i] = (p & 0xFFFF) * 124;
        }
        for (int i = tid; i < nrows; i += 512)
            sTs[i] = __ldg(&ts[cr + i]);
        __syncthreads();

        for (int rl = wid; rl < nrows; rl += 16) {
            const int t = sTs[rl];
            const int ti = t * 5 + L.la;
            const float4 A  = __ldg(&g_tabA[ti]);
            const float4 Bv = __ldg(&g_tabB[ti]);
            const float2 Cv = __ldg(&g_tabC[ti]);
            const float4 Dv = __ldg(&g_tabD[ti]);
            const bool t0 = (t == 0);
            const int pack = sPack[rl * F_TOT + feat];
            const int hotc = pack >> 16, winc = pack & 0xFFFF;
            const bool h0 = (hotc == C0), h1 = (hotc == C0 + 1);
            const bool w0 = (winc == C0), w1 = (winc == C0 + 1);
            const bool same = (hotc == winc);
            const float n1 = same ? Dv.x : Dv.z;
            const float inv1k = (same ? Dv.y : Dv.w) * 1000.f;

            // ---- gather: 40 fp16 winner rows, 4 interleaved half2 accumulators ----
            const int4* op = (const int4*)(sOff + rl * F_TOT);
            half2 a0 = __float2half2_rn(0.f), a1 = a0, a2 = a0, a3 = a0;
#pragma unroll
            for (int q = 0; q < 10; q++) {
                int4 o = op[q];
                a0 = __hadd2(a0, *(const half2*)(sWb + o.x + cpb));
                a1 = __hadd2(a1, *(const half2*)(sWb + o.y + cpb));
                a2 = __hadd2(a2, *(const half2*)(sWb + o.z + cpb));
                a3 = __hadd2(a3, *(const half2*)(sWb + o.w + cpb));
            }
            const float2 w2 = __half22float2(__hadd2(__hadd2(a0, a1), __hadd2(a2, a3)));

            const float2 te = *(const float2*)(temb + (size_t)t * D_TOT + C0);
            const float p0 = LOGEPS * (cs2.x - w2.x) + b2.x + te.x;
            const float p1 = LOGEPS * (cs2.y - w2.y) + b2.y + te.y;

            // per-segment softmax (exp-domain)
            float m = valid ? fmaxf(p0, p1) : NEG;
            m = segMax(m, L.widthL);
            const float E0 = valid ? __expf(p0 - m) : 0.f;
            const float E1 = valid ? __expf(p1 - m) : 0.f;
            const float s = segSum(E0 + E1, L.widthL);
            const float invs = __fdividef(1.f, s);
            const float lses = __logf(s);

            // exp(e2) via table FMA
            const float xe20 = E0 * invs * Cv.x + Cv.y;
            const float xe21 = E1 * invs * Cv.x + Cv.y;
            const float e2l0 = t0 ? (p0 - m - lses) : __logf(xe20);
            const float e2l1 = t0 ? (p1 - m - lses) : __logf(xe21);

            const float qo0e = w0 ? A.w : A.y, qo1e = w1 ? A.w : A.y;
            const float ev0l = h0 ? Bv.x : Bv.z, ev1l = h1 ? Bv.x : Bv.z;
            const float ev0e = h0 ? Bv.y : Bv.w, ev1e = h1 ? Bv.y : Bv.w;

            const float ew0 = xe20 * qo0e, ew1 = xe21 * qo1e;
            const float s2 = segSum((valid ? ew0 : 0.f) + (valid ? ew1 : 0.f), L.widthL);
            const float n2 = __logf(s2);
            const float dn = n2 - n1;

            if (!t0) {
                const float eu0 = ev0e * qo0e, eu1 = ev1e * qo1e;
                const float klsum = eu0 * (ev0l - e2l0 + dn) + eu1 * (ev1l - e2l1 + dn);
                lacc += valid ? (klsum * inv1k) : 0.f;
            } else {
                const float qo0l = w0 ? A.z : A.x, qo1l = w1 ? A.z : A.x;
                const float deL = (h0 ? (n2 - e2l0 - qo0l) : 0.f) + (h1 ? (n2 - e2l1 - qo1l) : 0.f);
                lacc += valid ? (deL * 1000.f) : 0.f;
            }
        }
    }

#pragma unroll
    for (int d = 1; d < 32; d <<= 1)
        lacc += __shfl_xor_sync(FULLM, lacc, d);
    if (lane == 0)
        g_part[(g * NTILES + blockIdx.x) * 16 + wid] = lacc;
}

// ---------------- deterministic single-kernel mean ----------------
__global__ void k_red(float* __restrict__ out, int B) {
    __shared__ float s[1024];
    const int tid = threadIdx.x;
    const int n = NTILES * GROUPS * 16;
    float a = 0.f;
    for (int i = tid; i < n; i += 1024) a += g_part[i];
    s[tid] = a;
    __syncthreads();
    for (int off = 512; off > 0; off >>= 1) {
        if (tid < off) s[tid] += s[tid + off];
        __syncthreads();
    }
    if (tid == 0) out[0] = s[0] / (float)B + g_prior;
}

// ---------------- launch ----------------
extern "C" void kernel_launch(void* const* d_in, const int* in_sizes, int n_in,
                              void* d_out, int out_size) {
    const int*   x0   = (const int*)d_in[0];
    const int*   ts   = (const int*)d_in[1];
    const float* uni  = (const float*)d_in[2];
    const float* W    = (const float*)d_in[3];
    const float* bias = (const float*)d_in[4];
    const float* temb = (const float*)d_in[5];
    float* out = (float*)d_out;
    const int B = in_sizes[1];

    cudaFuncSetAttribute(k_fuse, cudaFuncAttributeMaxDynamicSharedMemorySize, SMEM_K2);

    k_prep<<<6, 1024>>>();
    k_sample<<<296, 1024>>>(x0, ts, uni, B);
    dim3 gridF(NTILES, GROUPS);
    k_fuse<<<gridF, 512, SMEM_K2>>>(ts, W, bias, temb, B);
    k_red<<<1, 1024>>>(out, B);
}